// round 15
// baseline (speedup 1.0000x reference)
#include <cuda_runtime.h>

// RNNEncoder: 2-layer GRU, H=64, N=512 seqs (B=16 x C=32), L=2048, scalar input layer0.
// R10: shared-memory-wavefront bound fix. 128 CTAs x 4 seqs, 288 threads (9 warps).
// Each lane owns TWO weight rows (j=lane, lane+32) -> same h loads feed 2x FFMA2,
// halving total LDS.128 wavefronts per SM vs the 576-thread version.
// Weights in registers (128 regs/thread, cap 224 @288thr), h in shared,
// packed fma.rn.f32x2. Layer-1 pipelined one step behind layer-0.

#define LSEQ 2048
#define HD 64
#define CCH 32
#define SEQ_PER_CTA 4
#define NTHREADS 288

typedef unsigned long long u64;

__device__ __forceinline__ void upk(u64 v, float& x, float& y) {
    asm("mov.b64 {%0,%1}, %2;" : "=f"(x), "=f"(y) : "l"(v));
}
__device__ __forceinline__ u64 fma2(u64 a, u64 b, u64 c) {
    u64 d; asm("fma.rn.f32x2 %0, %1, %2, %3;" : "=l"(d) : "l"(a), "l"(b), "l"(c)); return d;
}

__device__ __forceinline__ float sigf(float x) {
    return __fdividef(1.f, 1.f + __expf(-x));
}
// tanh(x) = 2*sigmoid(2x) - 1 (exact identity)
__device__ __forceinline__ float tanh_fast(float x) {
    return fmaf(2.f, __fdividef(1.f, 1.f + __expf(-2.f * x)), -1.f);
}

__global__ void __launch_bounds__(NTHREADS, 1) gru2_kernel(
    const float* __restrict__ x,
    const float* __restrict__ w_ih0, const float* __restrict__ w_hh0,
    const float* __restrict__ b0,    const float* __restrict__ bn0,
    const float* __restrict__ w_ih1, const float* __restrict__ w_hh1,
    const float* __restrict__ b1,    const float* __restrict__ bn1,
    float* __restrict__ out)
{
    __shared__ __align__(16) float h0sh[SEQ_PER_CTA][HD];
    __shared__ __align__(16) float h1sh[SEQ_PER_CTA][HD];
    __shared__ __align__(16) float stage[9][SEQ_PER_CTA][HD];
    __shared__ float xsh[SEQ_PER_CTA][LSEQ];

    const int tid  = threadIdx.x;
    const int role = tid >> 5;          // warp id 0..8
    const int lane = tid & 31;
    // role 0..2: W_hh0 gate g (reads h0); role 3..5: W_hh1 gate g (reads h1);
    // role 6..8: W_ih1 gate g (reads h0)
    const int g = (role >= 6) ? (role - 6) : ((role >= 3) ? (role - 3) : role);
    const float* mat = (role < 3) ? w_hh0 : ((role < 6) ? w_hh1 : w_ih1);
    const float* row0 = mat + (g * HD + lane) * HD;
    const float* row1 = mat + (g * HD + lane + 32) * HD;

    // two weight rows in registers as 2 x 32 packed f32x2
    u64 wr0[32], wr1[32];
#pragma unroll
    for (int i = 0; i < 16; i++) {
        ulonglong2 w = ((const ulonglong2*)row0)[i];
        wr0[2 * i] = w.x; wr0[2 * i + 1] = w.y;
    }
#pragma unroll
    for (int i = 0; i < 16; i++) {
        ulonglong2 w = ((const ulonglong2*)row1)[i];
        wr1[2 * i] = w.x; wr1[2 * i + 1] = w.y;
    }
    const float biasc0 = (role >= 6) ? b1[g * HD + lane]      : 0.f;
    const float biasc1 = (role >= 6) ? b1[g * HD + lane + 32] : 0.f;

    // combine-phase per-j constants (used by tid<256; j = tid&63)
    const int jc = tid & 63;
    const float c_wir = w_ih0[jc],       c_wiz = w_ih0[HD + jc], c_win = w_ih0[2 * HD + jc];
    const float c_br  = b0[jc],          c_bz  = b0[HD + jc],    c_bn  = b0[2 * HD + jc];
    const float c_bnn0 = bn0[jc],        c_bnn1 = bn1[jc];

    // stage x for this CTA's 4 sequences into shared
    const int nbase = blockIdx.x * SEQ_PER_CTA;
    for (int i = tid; i < SEQ_PER_CTA * LSEQ; i += NTHREADS) {
        int s = i >> 11, t = i & (LSEQ - 1);
        int n = nbase + s;
        int b = n >> 5, c = n & (CCH - 1);
        xsh[s][t] = x[(size_t)b * LSEQ * CCH + (size_t)t * CCH + c];
    }
    for (int i = tid; i < SEQ_PER_CTA * HD; i += NTHREADS) {
        ((float*)h0sh)[i] = 0.f;
        ((float*)h1sh)[i] = 0.f;
    }
    __syncthreads();

    for (int u = 0; u <= LSEQ; ++u) {
        // ---- Phase A: 9 warps x 2 rows x 4 seqs; h loads shared across both rows ----
        const float* hb = (role >= 3 && role < 6) ? &h1sh[0][0] : &h0sh[0][0];
        const ulonglong2* hv0 = (const ulonglong2*)(hb + 0 * HD);
        const ulonglong2* hv1 = (const ulonglong2*)(hb + 1 * HD);
        const ulonglong2* hv2 = (const ulonglong2*)(hb + 2 * HD);
        const ulonglong2* hv3 = (const ulonglong2*)(hb + 3 * HD);
        u64 p0 = 0ull, p1 = 0ull, p2 = 0ull, p3 = 0ull;   // row0, seqs 0..3
        u64 q0 = 0ull, q1 = 0ull, q2 = 0ull, q3 = 0ull;   // row1, seqs 0..3
#pragma unroll
        for (int i = 0; i < 16; i++) {
            ulonglong2 v0 = hv0[i];
            ulonglong2 v1 = hv1[i];
            ulonglong2 v2 = hv2[i];
            ulonglong2 v3 = hv3[i];
            u64 wa = wr0[2 * i], wb = wr0[2 * i + 1];
            u64 wc = wr1[2 * i], wd = wr1[2 * i + 1];
            p0 = fma2(wa, v0.x, p0); p0 = fma2(wb, v0.y, p0);
            p1 = fma2(wa, v1.x, p1); p1 = fma2(wb, v1.y, p1);
            p2 = fma2(wa, v2.x, p2); p2 = fma2(wb, v2.y, p2);
            p3 = fma2(wa, v3.x, p3); p3 = fma2(wb, v3.y, p3);
            q0 = fma2(wc, v0.x, q0); q0 = fma2(wd, v0.y, q0);
            q1 = fma2(wc, v1.x, q1); q1 = fma2(wd, v1.y, q1);
            q2 = fma2(wc, v2.x, q2); q2 = fma2(wd, v2.y, q2);
            q3 = fma2(wc, v3.x, q3); q3 = fma2(wd, v3.y, q3);
        }
        {
            float lo, hi;
            upk(p0, lo, hi); stage[role][0][lane]      = lo + hi + biasc0;
            upk(p1, lo, hi); stage[role][1][lane]      = lo + hi + biasc0;
            upk(p2, lo, hi); stage[role][2][lane]      = lo + hi + biasc0;
            upk(p3, lo, hi); stage[role][3][lane]      = lo + hi + biasc0;
            upk(q0, lo, hi); stage[role][0][lane + 32] = lo + hi + biasc1;
            upk(q1, lo, hi); stage[role][1][lane + 32] = lo + hi + biasc1;
            upk(q2, lo, hi); stage[role][2][lane + 32] = lo + hi + biasc1;
            upk(q3, lo, hi); stage[role][3][lane + 32] = lo + hi + biasc1;
        }
        __syncthreads();

        // ---- Phase B: tid<256 does layer-0 (step u) AND layer-1 (step u-1) for (s,j) ----
        if (tid < 256) {
            const int s = tid >> 6;
            const int j = jc;
            if (u < LSEQ) {            // layer-0 combine
                float xv = xsh[s][u];
                float r  = sigf(fmaf(c_wir, xv, c_br) + stage[0][s][j]);
                float z  = sigf(fmaf(c_wiz, xv, c_bz) + stage[1][s][j]);
                float nn = tanh_fast(fmaf(c_win, xv, c_bn) + r * (stage[2][s][j] + c_bnn0));
                float h  = h0sh[s][j];
                h0sh[s][j] = nn + z * (h - nn);
            }
            if (u >= 1) {              // layer-1 combine for step u-1
                float r  = sigf(stage[6][s][j] + stage[3][s][j]);
                float z  = sigf(stage[7][s][j] + stage[4][s][j]);
                float nn = tanh_fast(stage[8][s][j] + r * (stage[5][s][j] + c_bnn1));
                float h  = h1sh[s][j];
                float hn = nn + z * (h - nn);
                h1sh[s][j] = hn;
                out[(size_t)(nbase + s) * LSEQ * HD + (size_t)(u - 1) * HD + j] = hn;
            }
        }
        __syncthreads();
    }
}

extern "C" void kernel_launch(void* const* d_in, const int* in_sizes, int n_in,
                              void* d_out, int out_size) {
    const float* x     = (const float*)d_in[0];
    const float* w_ih0 = (const float*)d_in[1];
    const float* w_hh0 = (const float*)d_in[2];
    const float* b0    = (const float*)d_in[3];
    const float* bn0   = (const float*)d_in[4];
    const float* w_ih1 = (const float*)d_in[5];
    const float* w_hh1 = (const float*)d_in[6];
    const float* b1    = (const float*)d_in[7];
    const float* bn1   = (const float*)d_in[8];
    float* out = (float*)d_out;

    gru2_kernel<<<128, NTHREADS>>>(x, w_ih0, w_hh0, b0, bn0,
                                   w_ih1, w_hh1, b1, bn1, out);
}